// round 14
// baseline (speedup 1.0000x reference)
#include <cuda_runtime.h>
#include <cuda_bf16.h>
#include <cuda_fp16.h>

// ---------------------------------------------------------------------------
// Trivariate cubic B-spline evaluation, cell-sorted, 4-kernel + 1-memset.
// Windows in fp16 (window-dim half2 pairs); eval x-dots computed in half2
// SIMD (HMUL2/HFMA2) with fp32 even/odd accumulation.
//   0) memset  : zero 123KB histogram (DMA graph node)
//   1) histwin : histogram queries (rank capture) + pack fp16 windows +
//                build 1KB global knot/rcp tables (one block)
//   2) scan    : single-pass exclusive scan, decoupled one-warp epilogue,
//                monotone modulo ticket (graph-replay safe)
//   3) scatter : pos = choff + excl + rank (plain loads, no atomics)
//   4) eval    : closed-form cardinal basis (interior) / global-table
//                Cox-de Boor (boundary); half2 SIMD dots; direct stores.
// ---------------------------------------------------------------------------

#define NC     64
#define NCEL   (NC * NC * NC)
#define NQMAX  1000000
#define NBIN   29768               // 8 * 61 * 61
#define CHUNK  1024
#define NCHUNK 30                  // ceil(NBIN/1024)
#define NBINP  (NCHUNK * CHUNK)    // 30720
#define WINBLK 1024                // NCEL / 256

__device__ uint4    g_wxy[NCEL];       // fp16 windows: {x0,x1}{x2,x3}{y0,y1}{y2,y3}
__device__ uint2    g_wz[NCEL];        // fp16 windows: {z0,z1}{z2,z3}
__device__ float4   g_sq[NQMAX];       // sorted queries {x,y,z,orig_idx}
__device__ unsigned g_qkey[NQMAX];     // packed (rank<<15) | key
__device__ int      g_hist[NBINP];     // counts -> excl offsets within chunk
__device__ int      g_bsum[NCHUNK];    // chunk totals
__device__ int      g_choff[NCHUNK];   // chunk exclusive offsets
__device__ int      g_sync;            // monotone scan ticket (never reset)
__device__ float    g_knots[3][68];    // knot vectors (L1-resident)
__device__ float    g_rcp[3][3][68];   // reciprocal denominators [axis][r-1][m]

// ---------------------------------------------------------------- utilities

__device__ __forceinline__ int cell_key(float x, float y, float z) {
    int cx = min(7,  max(0, (int)(x * 8.0f)));
    int cy = min(60, max(0, (int)(y * 61.0f)));
    int cz = min(60, max(0, (int)(z * 61.0f)));
    return cx + 8 * (cy + 61 * cz);            // < 29768 < 2^15
}

__device__ __forceinline__ int warp_incl_scan(int v, int lane) {
#pragma unroll
    for (int o = 1; o < 32; o <<= 1) {
        int u = __shfl_up_sync(0xffffffffu, v, o);
        if (lane >= o) v += u;
    }
    return v;
}

__device__ __forceinline__ unsigned pack_h2(float a, float b) {
    __half2 h = __floats2half2_rn(a, b);
    return *reinterpret_cast<unsigned*>(&h);
}

__device__ __forceinline__ __half2 as_h2(unsigned u) {
    return *reinterpret_cast<__half2*>(&u);
}

// ------------- 1) histogram (+rank capture) + window packing + knot tables

__global__ void histwin_kernel(const float* __restrict__ q,
                               const float* __restrict__ cp,
                               const float* __restrict__ tx,
                               const float* __restrict__ ty,
                               const float* __restrict__ tz,
                               int n, int qblocks) {
    int bid = blockIdx.x;
    if (bid < qblocks) {
        int i = bid * blockDim.x + threadIdx.x;
        if (i >= n) return;
        int key = cell_key(q[3 * i], q[3 * i + 1], q[3 * i + 2]);
        unsigned rank = (unsigned)atomicAdd(&g_hist[key], 1);
        g_qkey[i] = (unsigned)key | (rank << 15);
    } else if (bid < qblocks + WINBLK) {
        int i = (bid - qblocks) * blockDim.x + threadIdx.x;
        if (i >= NCEL) return;
        int ix0 = i & 63;
        if (ix0 > 60) return;
        const float* p = cp + (size_t)i * 3;
        uint4 rxy;
        rxy.x = pack_h2(p[0], p[3]);    // x0,x1
        rxy.y = pack_h2(p[6], p[9]);    // x2,x3
        rxy.z = pack_h2(p[1], p[4]);    // y0,y1
        rxy.w = pack_h2(p[7], p[10]);   // y2,y3
        uint2 rz;
        rz.x  = pack_h2(p[2], p[5]);    // z0,z1
        rz.y  = pack_h2(p[8], p[11]);   // z2,z3
        g_wxy[i] = rxy;
        g_wz[i]  = rz;
    } else {
        const float* tt[3] = {tx, ty, tz};
        for (int w = threadIdx.x; w < 3 * 68; w += blockDim.x) {
            int a = w / 68, m = w - a * 68;
            g_knots[a][m] = tt[a][m];
        }
        for (int w = threadIdx.x; w < 3 * 3 * 68; w += blockDim.x) {
            int a = w / 204;
            int rem = w - a * 204;
            int r = rem / 68 + 1;
            int m = rem - (r - 1) * 68;
            float d = (m >= r) ? (tt[a][m] - tt[a][m - r]) : 0.0f;
            g_rcp[a][r - 1][m] = (d > 0.0f) ? (1.0f / d) : 0.0f;
        }
    }
}

// -------------------------------------- 2) single-pass scan, safe epilogue

__global__ __launch_bounds__(CHUNK)
void scan_kernel() {
    __shared__ int swarp[32];
    __shared__ int strigger;
    int t = threadIdx.x;
    int lane = t & 31, w = t >> 5;
    int g = blockIdx.x * CHUNK + t;

    int v = g_hist[g];
    int incl = warp_incl_scan(v, lane);
    if (lane == 31) swarp[w] = incl;
    __syncthreads();
    if (w == 0) {
        int s = swarp[lane];
        int si = warp_incl_scan(s, lane);
        swarp[lane] = si - s;
        if (lane == 31) g_bsum[blockIdx.x] = si;   // chunk total
    }
    __syncthreads();
    g_hist[g] = swarp[w] + incl - v;               // exclusive within chunk

    __threadfence();
    if (t == 0) strigger = (atomicAdd(&g_sync, 1) % NCHUNK) == NCHUNK - 1;
    __syncthreads();                                // full block, always reached
    if (!strigger || w != 0) return;                // one warp of last block

    volatile int* bs = g_bsum;
    int carry = 0;
#pragma unroll
    for (int base = 0; base < NCHUNK; base += 32) {
        int idx = base + lane;
        int bv = (idx < NCHUNK) ? bs[idx] : 0;
        int bincl = warp_incl_scan(bv, lane);
        if (idx < NCHUNK) g_choff[idx] = carry + bincl - bv;
        carry += __shfl_sync(0xffffffffu, bincl, 31);
    }
}

// ------------------------------------------- 3) scatter (atomic-free)

__global__ __launch_bounds__(256)
void scatter_kernel(const float* __restrict__ q, int n) {
    int i = blockIdx.x * blockDim.x + threadIdx.x;
    if (i >= n) return;
    unsigned pk = g_qkey[i];                       // coalesced
    int key  = (int)(pk & 0x7FFFu);
    int rank = (int)(pk >> 15);
    float x = q[3 * i], y = q[3 * i + 1], z = q[3 * i + 2];
    int pos = g_choff[key >> 10] + g_hist[key] + rank;  // hist: L1-hot 123KB
    g_sq[pos] = make_float4(x, y, z, __int_as_float(i));
}

// -------------------------------------------------------------------- basis

__device__ __forceinline__ void bspline_basis4(int axis, float x,
                                               int& kout, float N[4]) {
    float xc = fminf(fmaxf(x, 0.0f), 1.0f);
    float xs = xc * 61.0f;
    int k = 3 + (int)xs;
    k = min(k, 63);
    kout = k;

    if (k >= 5 && k <= 61) {
        float u = xs - (float)(k - 3);        // in [0,1)
        float v = 1.0f - u;
        float u2 = u * u, v2 = v * v;
        N[0] = (1.0f / 6.0f) * v2 * v;
        N[3] = (1.0f / 6.0f) * u2 * u;
        N[1] = (2.0f / 3.0f) - u2 * (1.0f - 0.5f * u);
        N[2] = (2.0f / 3.0f) - v2 * (1.0f - 0.5f * v);
        return;
    }

    const float* t = g_knots[axis];
    float left[4], right[4];
    N[0] = 1.0f;
#pragma unroll
    for (int r = 1; r <= 3; ++r) {
        left[r]  = xc - __ldg(&t[k + 1 - r]);
        right[r] = __ldg(&t[k + r]) - xc;
        float saved = 0.0f;
        const float* rc = g_rcp[axis][r - 1];
#pragma unroll
        for (int j = 0; j < r; ++j) {
            float temp = N[j] * __ldg(&rc[k + j + 1]);
            N[j] = fmaf(right[j + 1], temp, saved);
            saved = left[r - j] * temp;
        }
        N[r] = saved;
    }
}

// --------------------------------------------------------------------- eval

__global__ __launch_bounds__(256)
void spline_eval_kernel(float* __restrict__ out, int n) {
    int i = blockIdx.x * blockDim.x + threadIdx.x;
    if (i >= n) return;

    float4 qv = g_sq[i];
    int oi = __float_as_int(qv.w);

    int kx, ky, kz;
    float bx[4], by[4], bz[4];
    bspline_basis4(0, qv.x, kx, bx);
    bspline_basis4(1, qv.y, ky, by);
    bspline_basis4(2, qv.z, kz, bz);

    // bx packed for half2 SIMD dots (lanes = even/odd x-taps)
    __half2 hbx01 = __floats2half2_rn(bx[0], bx[1]);
    __half2 hbx23 = __floats2half2_rn(bx[2], bx[3]);

    int base = (kx - 3) + (ky - 3) * 64 + (kz - 3) * 4096;

    float axe = 0.0f, axo = 0.0f;   // even/odd partial accumulators
    float aye = 0.0f, ayo = 0.0f;
    float aze = 0.0f, azo = 0.0f;
#pragma unroll
    for (int c = 0; c < 4; ++c) {
#pragma unroll
        for (int b = 0; b < 4; ++b) {
            int w = base + b * 64 + c * 4096;
            float wbc = by[b] * bz[c];
            uint4 rxy = __ldg(&g_wxy[w]);
            uint2 rz  = __ldg(&g_wz[w]);
            __half2 sx = __hfma2(hbx23, as_h2(rxy.y), __hmul2(hbx01, as_h2(rxy.x)));
            __half2 sy = __hfma2(hbx23, as_h2(rxy.w), __hmul2(hbx01, as_h2(rxy.z)));
            __half2 sz = __hfma2(hbx23, as_h2(rz.y),  __hmul2(hbx01, as_h2(rz.x)));
            float2 fx = __half22float2(sx);
            float2 fy = __half22float2(sy);
            float2 fz = __half22float2(sz);
            axe = fmaf(wbc, fx.x, axe);  axo = fmaf(wbc, fx.y, axo);
            aye = fmaf(wbc, fy.x, aye);  ayo = fmaf(wbc, fy.y, ayo);
            aze = fmaf(wbc, fz.x, aze);  azo = fmaf(wbc, fz.y, azo);
        }
    }

    out[3 * oi + 0] = axe + axo;
    out[3 * oi + 1] = aye + ayo;
    out[3 * oi + 2] = aze + azo;
}

// ---------------------------------------------------------------- launcher

extern "C" void kernel_launch(void* const* d_in, const int* in_sizes, int n_in,
                              void* d_out, int out_size) {
    const float* queries = (const float*)d_in[0];
    const float* cp      = (const float*)d_in[1];
    const float* tx      = (const float*)d_in[2];
    const float* ty      = (const float*)d_in[3];
    const float* tz      = (const float*)d_in[4];
    float* out           = (float*)d_out;

    int nq = in_sizes[0] / 3;
    int qb = (nq + 255) / 256;

    void* hist_ptr = nullptr;
    cudaGetSymbolAddress(&hist_ptr, g_hist);       // address query, no alloc
    cudaMemsetAsync(hist_ptr, 0, NBINP * sizeof(int), 0);

    histwin_kernel<<<qb + WINBLK + 1, 256>>>(queries, cp, tx, ty, tz, nq, qb);
    scan_kernel<<<NCHUNK, CHUNK>>>();
    scatter_kernel<<<qb, 256>>>(queries, nq);
    spline_eval_kernel<<<qb, 256>>>(out, nq);
}

// round 15
// speedup vs baseline: 1.3666x; 1.3666x over previous
#include <cuda_runtime.h>
#include <cuda_bf16.h>
#include <cuda_fp16.h>

// ---------------------------------------------------------------------------
// Trivariate cubic B-spline evaluation, cell-sorted, 4-kernel + 1-memset.
// R13 structure + arithmetic (fp32 dots on fp16 windows); eval processes
// TWO independent queries per thread for latency overlap.
//   0) memset  : zero 123KB histogram (DMA graph node)
//   1) histwin : histogram queries (rank capture) + pack fp16 windows +
//                build 1KB global knot/rcp tables (one block)
//   2) scan    : single-pass exclusive scan, decoupled one-warp epilogue,
//                monotone modulo ticket (graph-replay safe)
//   3) scatter : pos = choff + excl + rank (plain loads, no atomics)
//   4) eval    : closed-form cardinal basis (interior) / global-table
//                Cox-de Boor (boundary); fp32 dots; 2 queries/thread;
//                direct scattered stores.
// ---------------------------------------------------------------------------

#define NC     64
#define NCEL   (NC * NC * NC)
#define NQMAX  1000000
#define NBIN   29768               // 8 * 61 * 61
#define CHUNK  1024
#define NCHUNK 30                  // ceil(NBIN/1024)
#define NBINP  (NCHUNK * CHUNK)    // 30720
#define WINBLK 1024                // NCEL / 256

__device__ uint4    g_wxy[NCEL];       // fp16 windows: {x0,x1}{x2,x3}{y0,y1}{y2,y3}
__device__ uint2    g_wz[NCEL];        // fp16 windows: {z0,z1}{z2,z3}
__device__ float4   g_sq[NQMAX];       // sorted queries {x,y,z,orig_idx}
__device__ unsigned g_qkey[NQMAX];     // packed (rank<<15) | key
__device__ int      g_hist[NBINP];     // counts -> excl offsets within chunk
__device__ int      g_bsum[NCHUNK];    // chunk totals
__device__ int      g_choff[NCHUNK];   // chunk exclusive offsets
__device__ int      g_sync;            // monotone scan ticket (never reset)
__device__ float    g_knots[3][68];    // knot vectors (L1-resident)
__device__ float    g_rcp[3][3][68];   // reciprocal denominators [axis][r-1][m]

// ---------------------------------------------------------------- utilities

__device__ __forceinline__ int cell_key(float x, float y, float z) {
    int cx = min(7,  max(0, (int)(x * 8.0f)));
    int cy = min(60, max(0, (int)(y * 61.0f)));
    int cz = min(60, max(0, (int)(z * 61.0f)));
    return cx + 8 * (cy + 61 * cz);            // < 29768 < 2^15
}

__device__ __forceinline__ int warp_incl_scan(int v, int lane) {
#pragma unroll
    for (int o = 1; o < 32; o <<= 1) {
        int u = __shfl_up_sync(0xffffffffu, v, o);
        if (lane >= o) v += u;
    }
    return v;
}

__device__ __forceinline__ unsigned pack_h2(float a, float b) {
    __half2 h = __floats2half2_rn(a, b);
    return *reinterpret_cast<unsigned*>(&h);
}

// ------------- 1) histogram (+rank capture) + window packing + knot tables

__global__ void histwin_kernel(const float* __restrict__ q,
                               const float* __restrict__ cp,
                               const float* __restrict__ tx,
                               const float* __restrict__ ty,
                               const float* __restrict__ tz,
                               int n, int qblocks) {
    int bid = blockIdx.x;
    if (bid < qblocks) {
        int i = bid * blockDim.x + threadIdx.x;
        if (i >= n) return;
        int key = cell_key(q[3 * i], q[3 * i + 1], q[3 * i + 2]);
        unsigned rank = (unsigned)atomicAdd(&g_hist[key], 1);
        g_qkey[i] = (unsigned)key | (rank << 15);
    } else if (bid < qblocks + WINBLK) {
        int i = (bid - qblocks) * blockDim.x + threadIdx.x;
        if (i >= NCEL) return;
        int ix0 = i & 63;
        if (ix0 > 60) return;
        const float* p = cp + (size_t)i * 3;
        uint4 rxy;
        rxy.x = pack_h2(p[0], p[3]);    // x0,x1
        rxy.y = pack_h2(p[6], p[9]);    // x2,x3
        rxy.z = pack_h2(p[1], p[4]);    // y0,y1
        rxy.w = pack_h2(p[7], p[10]);   // y2,y3
        uint2 rz;
        rz.x  = pack_h2(p[2], p[5]);    // z0,z1
        rz.y  = pack_h2(p[8], p[11]);   // z2,z3
        g_wxy[i] = rxy;
        g_wz[i]  = rz;
    } else {
        const float* tt[3] = {tx, ty, tz};
        for (int w = threadIdx.x; w < 3 * 68; w += blockDim.x) {
            int a = w / 68, m = w - a * 68;
            g_knots[a][m] = tt[a][m];
        }
        for (int w = threadIdx.x; w < 3 * 3 * 68; w += blockDim.x) {
            int a = w / 204;
            int rem = w - a * 204;
            int r = rem / 68 + 1;
            int m = rem - (r - 1) * 68;
            float d = (m >= r) ? (tt[a][m] - tt[a][m - r]) : 0.0f;
            g_rcp[a][r - 1][m] = (d > 0.0f) ? (1.0f / d) : 0.0f;
        }
    }
}

// -------------------------------------- 2) single-pass scan, safe epilogue

__global__ __launch_bounds__(CHUNK)
void scan_kernel() {
    __shared__ int swarp[32];
    __shared__ int strigger;
    int t = threadIdx.x;
    int lane = t & 31, w = t >> 5;
    int g = blockIdx.x * CHUNK + t;

    int v = g_hist[g];
    int incl = warp_incl_scan(v, lane);
    if (lane == 31) swarp[w] = incl;
    __syncthreads();
    if (w == 0) {
        int s = swarp[lane];
        int si = warp_incl_scan(s, lane);
        swarp[lane] = si - s;
        if (lane == 31) g_bsum[blockIdx.x] = si;   // chunk total
    }
    __syncthreads();
    g_hist[g] = swarp[w] + incl - v;               // exclusive within chunk

    __threadfence();
    if (t == 0) strigger = (atomicAdd(&g_sync, 1) % NCHUNK) == NCHUNK - 1;
    __syncthreads();                                // full block, always reached
    if (!strigger || w != 0) return;                // one warp of last block

    volatile int* bs = g_bsum;
    int carry = 0;
#pragma unroll
    for (int base = 0; base < NCHUNK; base += 32) {
        int idx = base + lane;
        int bv = (idx < NCHUNK) ? bs[idx] : 0;
        int bincl = warp_incl_scan(bv, lane);
        if (idx < NCHUNK) g_choff[idx] = carry + bincl - bv;
        carry += __shfl_sync(0xffffffffu, bincl, 31);
    }
}

// ------------------------------------------- 3) scatter (atomic-free)

__global__ __launch_bounds__(256)
void scatter_kernel(const float* __restrict__ q, int n) {
    int i = blockIdx.x * blockDim.x + threadIdx.x;
    if (i >= n) return;
    unsigned pk = g_qkey[i];                       // coalesced
    int key  = (int)(pk & 0x7FFFu);
    int rank = (int)(pk >> 15);
    float x = q[3 * i], y = q[3 * i + 1], z = q[3 * i + 2];
    int pos = g_choff[key >> 10] + g_hist[key] + rank;  // hist: L1-hot 123KB
    g_sq[pos] = make_float4(x, y, z, __int_as_float(i));
}

// -------------------------------------------------------------------- basis

__device__ __forceinline__ void bspline_basis4(int axis, float x,
                                               int& kout, float N[4]) {
    float xc = fminf(fmaxf(x, 0.0f), 1.0f);
    float xs = xc * 61.0f;
    int k = 3 + (int)xs;
    k = min(k, 63);
    kout = k;

    if (k >= 5 && k <= 61) {
        float u = xs - (float)(k - 3);        // in [0,1)
        float v = 1.0f - u;
        float u2 = u * u, v2 = v * v;
        N[0] = (1.0f / 6.0f) * v2 * v;
        N[3] = (1.0f / 6.0f) * u2 * u;
        N[1] = (2.0f / 3.0f) - u2 * (1.0f - 0.5f * u);
        N[2] = (2.0f / 3.0f) - v2 * (1.0f - 0.5f * v);
        return;
    }

    const float* t = g_knots[axis];
    float left[4], right[4];
    N[0] = 1.0f;
#pragma unroll
    for (int r = 1; r <= 3; ++r) {
        left[r]  = xc - __ldg(&t[k + 1 - r]);
        right[r] = __ldg(&t[k + r]) - xc;
        float saved = 0.0f;
        const float* rc = g_rcp[axis][r - 1];
#pragma unroll
        for (int j = 0; j < r; ++j) {
            float temp = N[j] * __ldg(&rc[k + j + 1]);
            N[j] = fmaf(right[j + 1], temp, saved);
            saved = left[r - j] * temp;
        }
        N[r] = saved;
    }
}

// ----------------------------- eval: one query (R13 arithmetic, unchanged)

__device__ __forceinline__ void eval_one(int i, float* __restrict__ out) {
    float4 qv = g_sq[i];
    int oi = __float_as_int(qv.w);

    int kx, ky, kz;
    float bx[4], by[4], bz[4];
    bspline_basis4(0, qv.x, kx, bx);
    bspline_basis4(1, qv.y, ky, by);
    bspline_basis4(2, qv.z, kz, bz);

    int base = (kx - 3) + (ky - 3) * 64 + (kz - 3) * 4096;

    float ax = 0.0f, ay = 0.0f, az = 0.0f;
#pragma unroll
    for (int c = 0; c < 4; ++c) {
#pragma unroll
        for (int b = 0; b < 4; ++b) {
            int w = base + b * 64 + c * 4096;
            float wbc = by[b] * bz[c];
            uint4 rxy = __ldg(&g_wxy[w]);
            uint2 rz  = __ldg(&g_wz[w]);
            float2 x01 = __half22float2(*reinterpret_cast<__half2*>(&rxy.x));
            float2 x23 = __half22float2(*reinterpret_cast<__half2*>(&rxy.y));
            float2 y01 = __half22float2(*reinterpret_cast<__half2*>(&rxy.z));
            float2 y23 = __half22float2(*reinterpret_cast<__half2*>(&rxy.w));
            float2 z01 = __half22float2(*reinterpret_cast<__half2*>(&rz.x));
            float2 z23 = __half22float2(*reinterpret_cast<__half2*>(&rz.y));
            float sx = fmaf(bx[3], x23.y, fmaf(bx[2], x23.x, fmaf(bx[1], x01.y, bx[0] * x01.x)));
            float sy = fmaf(bx[3], y23.y, fmaf(bx[2], y23.x, fmaf(bx[1], y01.y, bx[0] * y01.x)));
            float sz = fmaf(bx[3], z23.y, fmaf(bx[2], z23.x, fmaf(bx[1], z01.y, bx[0] * z01.x)));
            ax = fmaf(wbc, sx, ax);
            ay = fmaf(wbc, sy, ay);
            az = fmaf(wbc, sz, az);
        }
    }

    out[3 * oi + 0] = ax;
    out[3 * oi + 1] = ay;
    out[3 * oi + 2] = az;
}

// Two independent queries per thread: doubled MLP, overlapped latency.
__global__ __launch_bounds__(256)
void spline_eval_kernel(float* __restrict__ out, int n) {
    int i0 = blockIdx.x * 512 + threadIdx.x;
    int i1 = i0 + 256;
    if (i0 < n) eval_one(i0, out);
    if (i1 < n) eval_one(i1, out);
}

// ---------------------------------------------------------------- launcher

extern "C" void kernel_launch(void* const* d_in, const int* in_sizes, int n_in,
                              void* d_out, int out_size) {
    const float* queries = (const float*)d_in[0];
    const float* cp      = (const float*)d_in[1];
    const float* tx      = (const float*)d_in[2];
    const float* ty      = (const float*)d_in[3];
    const float* tz      = (const float*)d_in[4];
    float* out           = (float*)d_out;

    int nq  = in_sizes[0] / 3;
    int qb  = (nq + 255) / 256;
    int qb2 = (nq + 511) / 512;

    void* hist_ptr = nullptr;
    cudaGetSymbolAddress(&hist_ptr, g_hist);       // address query, no alloc
    cudaMemsetAsync(hist_ptr, 0, NBINP * sizeof(int), 0);

    histwin_kernel<<<qb + WINBLK + 1, 256>>>(queries, cp, tx, ty, tz, nq, qb);
    scan_kernel<<<NCHUNK, CHUNK>>>();
    scatter_kernel<<<qb, 256>>>(queries, nq);
    spline_eval_kernel<<<qb2, 256>>>(out, nq);
}